// round 17
// baseline (speedup 1.0000x reference)
#include <cuda_runtime.h>
#include <math.h>

#define NCLS 40
#define QN 100
#define BN 4
#define HW 65536
#define THREADS 256
#define NWARP (THREADS/32)
#define PPT 4
#define PIX (THREADS*PPT)          // 1024 pixels per block
#define WPIX 128                   // pixels per warp
#define NC1 (NCLS+1)
#define QG 5                       // q-groups
#define QPG (QN/QG)                // 20 queries per group
#define NPIX (BN*HW)               // 262144 pixels
#define PIXBLK (HW/PIX)            // 64 pixel-blocks per image
#define NBLK_MAIN (QG*BN*PIXBLK)   // 1280
#define NBLK_COMB (NPIX/4/THREADS) // 256
#define FULL 0xffffffffu

// ---- scratch (device globals; no allocation allowed) ----
__device__ float g_inter[BN*QN*NCLS];
__device__ float g_src[BN*QN];
__device__ int   g_counts[BN*QN*NCLS];
__device__ int   g_tsum[BN*NCLS];
__device__ float g_ce_sum;
__device__ int   g_nvalid;
__device__ int   g_done;
// per-pixel per-group partials (~17 MB)
__device__ float4 g_pssum[QG][NPIX/4];
__device__ float4 g_pmax [QG][NPIX/4];
__device__ float4 g_pxt  [QG][NPIX/4];
__device__ uchar4 g_pamax[QG][NPIX/4];

__global__ void zero_k() {
    int i = blockIdx.x * blockDim.x + threadIdx.x;
    if (i < BN*QN*NCLS) { g_inter[i] = 0.f; g_counts[i] = 0; }
    if (i < BN*QN) g_src[i] = 0.f;
    if (i < BN*NCLS) g_tsum[i] = 0;
    if (i == 0) { g_ce_sum = 0.f; g_nvalid = 0; g_done = 0; }
}

// Streaming pass (R12-proven body): block = (q-group, image, 1024 pixels),
// 8 independent warps, warp-local counting sort + staging, no __syncthreads
// in the q-loop, shared-atomic run-merged commit.
__global__ __launch_bounds__(THREADS) void main_k(
    const float* __restrict__ masks, const int* __restrict__ targets)
{
    __shared__ __align__(16) float sig_sh[2][NWARP][WPIX];  // 8 KB double buffer
    __shared__ float inter_sh[QPG*NC1];                     // 3.3 KB
    __shared__ unsigned char cls_sorted[NWARP][WPIX];       // 1 KB
    __shared__ int wcnt[NWARP][NC1];
    __shared__ int wbase[NWARP][NC1];
    __shared__ int wcur[NWARP][NC1];

    const int tid  = threadIdx.x;
    const int lane = tid & 31;
    const int w    = tid >> 5;
    const int g    = blockIdx.x / (BN*PIXBLK);
    const int rem  = blockIdx.x % (BN*PIXBLK);
    const int img  = rem / PIXBLK;
    const int blk  = rem % PIXBLK;
    const int q0   = g*QPG;
    const int pixbase = img*HW + blk*PIX;

    for (int i = tid; i < QPG*NC1; i += THREADS) inter_sh[i] = 0.f;
    for (int i = lane; i < NC1; i += 32) wcnt[w][i] = 0;
    __syncthreads();   // only block barrier before the loop

    // ---- classes (4 contiguous pixels/lane) + WARP-LOCAL counting sort ----
    int myc[PPT], mypos[PPT];
    {
        int4 t4 = reinterpret_cast<const int4*>(targets + pixbase)[w*32 + lane];
        int tt[PPT] = {t4.x, t4.y, t4.z, t4.w};
        #pragma unroll
        for (int j = 0; j < PPT; j++) {
            myc[j] = ((unsigned)tt[j] < (unsigned)NCLS) ? tt[j] : NCLS; // 40 == ignore
            atomicAdd(&wcnt[w][myc[j]], 1);
        }
    }
    __syncwarp();
    if (lane == 0) {
        int r = 0;
        for (int c = 0; c < NC1; c++) { wbase[w][c] = r; r += wcnt[w][c]; }
    }
    __syncwarp();
    for (int i = lane; i < NC1; i += 32) wcur[w][i] = wbase[w][i];
    __syncwarp();
    #pragma unroll
    for (int j = 0; j < PPT; j++) {
        mypos[j] = atomicAdd(&wcur[w][myc[j]], 1);
        cls_sorted[w][mypos[j]] = (unsigned char)myc[j];
    }
    __syncwarp();
    const int k0 = (int)cls_sorted[w][lane*PPT + 0];
    const int k1 = (int)cls_sorted[w][lane*PPT + 1];
    const int k2 = (int)cls_sorted[w][lane*PPT + 2];
    const int k3 = (int)cls_sorted[w][lane*PPT + 3];

    float ssum[PPT], mmax[PPT], xt[PPT];
    int amax[PPT];
    #pragma unroll
    for (int j = 0; j < PPT; j++) { ssum[j] = 0.f; mmax[j] = -1e30f; xt[j] = 0.f; amax[j] = q0; }

    const float4* base4 = reinterpret_cast<const float4*>(
        masks + (size_t)img*QN*HW + (size_t)blk*PIX);
    const int stride4 = HW/4;
    const int myf4 = w*32 + lane;

    float4 cur = base4[(size_t)q0*stride4 + myf4];    // prefetch first q
    for (int qi = 0; qi < QPG; qi++) {
        const int q = q0 + qi;
        float4 nxt;
        if (qi + 1 < QPG) nxt = base4[(size_t)(q+1)*stride4 + myf4];
        else nxt = make_float4(0.f, 0.f, 0.f, 0.f);

        float xv[PPT] = {cur.x, cur.y, cur.z, cur.w};
        float* sbuf = sig_sh[qi & 1][w];
        #pragma unroll
        for (int j = 0; j < PPT; j++) {
            float x = xv[j];
            if (x > mmax[j]) { mmax[j] = x; amax[j] = q; }
            xt[j] = (q == myc[j]) ? x : xt[j];
            float t = __expf(x);               // one exp serves both lse and sigmoid
            ssum[j] += t;
            sbuf[mypos[j]] = __fdividef(t, 1.f + t);  // sigmoid -> sorted slot
        }
        __syncwarp();                          // warp-local scatter->gather
        // gather 4 consecutive class-sorted slots; run-merge; commit
        float4 v = reinterpret_cast<const float4*>(sbuf)[lane];
        float* ip = &inter_sh[qi*NC1];
        float s0 = v.x;
        if (k1 == k0) s0 += v.y;
        if (k2 == k0) s0 += v.z;
        if (k3 == k0) s0 += v.w;
        atomicAdd(ip + k0, s0);
        if (__any_sync(FULL, k3 != k0)) {
            if (k3 != k0) {
                float s3 = v.w;
                if (k2 == k3) s3 += v.z;
                if (k1 == k3) s3 += v.y;
                atomicAdd(ip + k3, s3);
            }
            bool m1 = (k1 != k0) & (k1 != k3);
            bool m2 = (k2 != k0) & (k2 != k3);
            if (__any_sync(FULL, m1 | m2)) {
                if (m1) atomicAdd(ip + k1, v.y);
                if (m2) atomicAdd(ip + k2, v.z);
            }
        }
        cur = nxt;
        // no barrier: double buffer; next q's syncwarp orders buffer reuse
    }

    // ---- write per-pixel partials for combine_k ----
    {
        const int p4 = pixbase/4 + myf4;
        g_pssum[g][p4] = make_float4(ssum[0], ssum[1], ssum[2], ssum[3]);
        g_pmax [g][p4] = make_float4(mmax[0], mmax[1], mmax[2], mmax[3]);
        g_pxt  [g][p4] = make_float4(xt[0], xt[1], xt[2], xt[3]);
        g_pamax[g][p4] = make_uchar4((unsigned char)amax[0], (unsigned char)amax[1],
                                     (unsigned char)amax[2], (unsigned char)amax[3]);
    }
    __syncthreads();   // orders all inter_sh atomics before flush

    // ---- flush inter_sh -> global (src_sum = sum over all 41 bins incl. ignore) ----
    for (int qi = tid; qi < QPG; qi += THREADS) {
        float ss = 0.f;
        const int q = q0 + qi;
        #pragma unroll 1
        for (int c = 0; c < NC1; c++) {
            float v = inter_sh[qi*NC1 + c];
            ss += v;
            if (c < NCLS) atomicAdd(&g_inter[(img*QN + q)*NCLS + c], v);
        }
        atomicAdd(&g_src[img*QN + q], ss);
    }
}

// Cross-group combine + (last block) final reduction. The fin logic runs in
// the last combine block on L2-hot data — one fewer kernel boundary.
__global__ __launch_bounds__(THREADS) void combine_k(
    const int* __restrict__ targets, const float* __restrict__ logits,
    float* __restrict__ out)
{
    __shared__ float s_ce[NWARP];
    __shared__ float s_nv[NWARP];
    __shared__ int hist[NCLS];
    const int tid = threadIdx.x;
    const int lane = tid & 31;
    const int wid = tid >> 5;
    const int j = blockIdx.x * THREADS + tid;      // float4 pixel group
    const int img = (int)(((size_t)blockIdx.x * THREADS * 4) >> 16);

    for (int i = tid; i < NCLS; i += THREADS) hist[i] = 0;
    __syncthreads();

    float4 ssum = g_pssum[0][j];
    float4 mmax = g_pmax [0][j];
    float4 xt   = g_pxt  [0][j];
    uchar4 am   = g_pamax[0][j];
    #pragma unroll
    for (int g = 1; g < QG; g++) {
        float4 s2 = g_pssum[g][j];
        float4 m2 = g_pmax [g][j];
        float4 x2 = g_pxt  [g][j];
        uchar4 a2 = g_pamax[g][j];
        ssum.x += s2.x; ssum.y += s2.y; ssum.z += s2.z; ssum.w += s2.w;
        xt.x += x2.x; xt.y += x2.y; xt.z += x2.z; xt.w += x2.w;
        if (m2.x > mmax.x) { mmax.x = m2.x; am.x = a2.x; }
        if (m2.y > mmax.y) { mmax.y = m2.y; am.y = a2.y; }
        if (m2.z > mmax.z) { mmax.z = m2.z; am.z = a2.z; }
        if (m2.w > mmax.w) { mmax.w = m2.w; am.w = a2.w; }
    }
    int4 t4 = reinterpret_cast<const int4*>(targets)[j];

    float ce_l = 0.f, nv = 0.f;
    int tt[PPT] = {t4.x, t4.y, t4.z, t4.w};
    float ssv[PPT] = {ssum.x, ssum.y, ssum.z, ssum.w};
    float xtv[PPT] = {xt.x, xt.y, xt.z, xt.w};
    int amv[PPT] = {am.x, am.y, am.z, am.w};
    #pragma unroll
    for (int k = 0; k < PPT; k++) {
        if ((unsigned)tt[k] < (unsigned)NCLS) {
            ce_l += __logf(ssv[k]) - xtv[k];       // lse - x[target]
            nv += 1.f;
            atomicAdd(&hist[tt[k]], 1);
            atomicAdd(&g_counts[(img*QN + amv[k])*NCLS + tt[k]], 1);
        }
    }
    #pragma unroll
    for (int o = 16; o > 0; o >>= 1) {
        ce_l += __shfl_xor_sync(FULL, ce_l, o);
        nv   += __shfl_xor_sync(FULL, nv, o);
    }
    if (lane == 0) { s_ce[wid] = ce_l; s_nv[wid] = nv; }
    __syncthreads();
    if (wid == 0) {
        float c = (lane < NWARP) ? s_ce[lane] : 0.f;
        float n = (lane < NWARP) ? s_nv[lane] : 0.f;
        #pragma unroll
        for (int o = 4; o > 0; o >>= 1) {
            c += __shfl_xor_sync(FULL, c, o);
            n += __shfl_xor_sync(FULL, n, o);
        }
        if (lane == 0) { atomicAdd(&g_ce_sum, c); atomicAdd(&g_nvalid, (int)n); }
    }
    for (int c = tid; c < NCLS; c += THREADS)
        if (hist[c]) atomicAdd(&g_tsum[img*NCLS + c], hist[c]);

    // ---- last-block-done: run the finalize here on L2-hot data ----
    __shared__ int s_last;
    __threadfence();
    __syncthreads();
    if (tid == 0) s_last = (atomicAdd(&g_done, 1) == NBLK_COMB - 1);
    __syncthreads();
    if (!s_last) return;

    __shared__ float tsum_sh[BN*NCLS];
    __shared__ float pres_sh[NCLS];
    __shared__ float redc[NWARP], redd[NWARP];
    for (int i = tid; i < BN*NCLS; i += THREADS) tsum_sh[i] = (float)g_tsum[i];
    __syncthreads();
    for (int c = tid; c < NCLS; c += THREADS) {
        float t = tsum_sh[c] + tsum_sh[NCLS+c] + tsum_sh[2*NCLS+c] + tsum_sh[3*NCLS+c];
        pres_sh[c] = (t > 0.f) ? 1.f : 0.f;
    }
    __syncthreads();

    // warp-per-item over 400 (b,q) items, NWARP warps round-robin
    float ce_acc = 0.f, dice_acc = 0.f;
    const int c1 = lane, c2 = lane + 32;
    for (int item = wid; item < BN*QN; item += NWARP) {
        const int b = item / QN;
        // mode label: packed-key warp max; ties -> smallest class
        const int* cp = &g_counts[item*NCLS];
        int v1 = __ldg(cp + c1);
        int v2 = (c2 < NCLS) ? __ldg(cp + c2) : 0;
        long long kk1 = ((long long)v1 << 16) | (NCLS - c1);
        long long kk2 = (c2 < NCLS) ? (((long long)v2 << 16) | (NCLS - c2)) : 0;
        long long key = kk1 > kk2 ? kk1 : kk2;
        #pragma unroll
        for (int o = 16; o > 0; o >>= 1) {
            long long other = __shfl_xor_sync(FULL, key, o);
            if (other > key) key = other;
        }
        int bestcnt = (int)(key >> 16);
        int bestc = NCLS - (int)(key & 0xffff);

        if (bestcnt > 0) {
            const float* lg = logits + item*NC1;
            float a = __ldg(lg + lane);
            float bb = (lane < NC1 - 32) ? __ldg(lg + lane + 32) : -1e30f;
            float m = fmaxf(a, bb);
            #pragma unroll
            for (int o = 16; o > 0; o >>= 1) m = fmaxf(m, __shfl_xor_sync(FULL, m, o));
            float s = __expf(a - m) + ((lane < NC1 - 32) ? __expf(bb - m) : 0.f);
            #pragma unroll
            for (int o = 16; o > 0; o >>= 1) s += __shfl_xor_sync(FULL, s, o);
            float lgb = __shfl_sync(FULL, (bestc < 32) ? a : bb, bestc & 31);
            float nll = m + __logf(s) - lgb;
            float p = __expf(-nll);
            float om = 1.f - p;
            if (lane == 0) ce_acc += om * om * nll;
        }

        float ssq = __ldg(&g_src[item]);
        float dl = pres_sh[c1] * 2.f * __ldg(&g_inter[item*NCLS + c1])
                   / (ssq + tsum_sh[b*NCLS + c1] + 1e-8f);
        if (c2 < NCLS)
            dl += pres_sh[c2] * 2.f * __ldg(&g_inter[item*NCLS + c2])
                  / (ssq + tsum_sh[b*NCLS + c2] + 1e-8f);
        dice_acc += dl;
    }
    #pragma unroll
    for (int o = 16; o > 0; o >>= 1) dice_acc += __shfl_xor_sync(FULL, dice_acc, o);
    if (lane == 0) { redc[wid] = ce_acc; redd[wid] = dice_acc; }
    __syncthreads();
    if (tid == 0) {
        float ce_tot = 0.f, dice_tot = 0.f, npres = 0.f;
        #pragma unroll
        for (int ww = 0; ww < NWARP; ww++) { ce_tot += redc[ww]; dice_tot += redd[ww]; }
        for (int c = 0; c < NCLS; c++) npres += pres_sh[c];
        float loss_ce = ce_tot / (float)(BN*QN);
        float ce_mask = g_ce_sum / fmaxf((float)g_nvalid, 1.f);
        float dice_loss = (npres - dice_tot / (float)(BN*QN)) / (float)NCLS;
        out[0] = 2.f*loss_ce + 5.f*ce_mask + 5.f*dice_loss;
    }
}

extern "C" void kernel_launch(void* const* d_in, const int* in_sizes, int n_in,
                              void* d_out, int out_size)
{
    const float* logits  = (const float*)d_in[0];   // [4,100,41] f32
    const float* masks   = (const float*)d_in[1];   // [4,100,256,256] f32
    const int*   targets = (const int*)d_in[2];     // [4,256,256] i32
    float* out = (float*)d_out;

    zero_k<<<(BN*QN*NCLS + 255)/256, 256>>>();
    main_k<<<NBLK_MAIN, THREADS>>>(masks, targets);
    combine_k<<<NBLK_COMB, THREADS>>>(targets, logits, out);
}